// round 16
// baseline (speedup 1.0000x reference)
#include <cuda_runtime.h>
#include <stdint.h>
#include <math.h>
#include <float.h>

// ---------------- problem constants ----------------
#define NN_   8192      // nodes
#define E1_   131072    // node-graph edges (= trace rows)
#define E2_   524288    // line-graph edges
#define DIN   256       // layer1 channels (4 heads x 64)
#define DED   128       // layer2 channels (4 heads x 32)
#define EPSV  1e-16f

// ---------------- scratch (static device, no allocs) ----------------
__device__ float g_xl     [(size_t)NN_ * DIN];
__device__ float g_xr     [(size_t)NN_ * DIN];
__device__ float g_den1   [(size_t)NN_ * 4];
__device__ float g_num    [(size_t)NN_ * DIN];  // layer-1 numerator
__device__ float g_xl2    [(size_t)E1_ * DED];
__device__ float g_xr2    [(size_t)E1_ * DED];
__device__ float g_gfeat  [(size_t)NN_ * DED];
__device__ float g_den2   [(size_t)E1_ * 4];

// ---------------- helpers ----------------
__device__ __forceinline__ float lrelu02(float x) { return x > 0.f ? x : 0.2f * x; }
__device__ __forceinline__ uint32_t to_tf32(float v) {
    uint32_t t;
    asm("cvt.rna.tf32.f32 %0, %1;" : "=r"(t) : "f"(v));
    return t;
}
__device__ __forceinline__ void cp16(uint32_t dst, const void* src) {
    asm volatile("cp.async.cg.shared.global [%0], [%1], 16;" :: "r"(dst), "l"(src));
}
__device__ __forceinline__ void red_add_v4(float* addr, float4 v) {
    asm volatile("red.global.add.v4.f32 [%0], {%1,%2,%3,%4};"
                 :: "l"(addr), "f"(v.x), "f"(v.y), "f"(v.z), "f"(v.w) : "memory");
}

// ---------------- tf32 GEMM tiles ----------------
#define TBM 128
#define TBN 128
#define TBK 32
#define STG 8960                 // floats per stage: 128*36 + 32*136
#define AS(S,M,K_) smem[(S)*STG + (M)*36 + (K_)]
#define BS(S,KK,N_) smem[(S)*STG + 4608 + (KK)*136 + (N_)]
#define ET(R,C) smem[(R)*132 + (C)]

struct Frag { float c[4][4][4]; };

// A source: if A1 != nullptr, rows come from A (k<128) or A1 (k>=128), each stride 128.
__device__ __forceinline__ void load_stage(float* smem, int s,
    const float* __restrict__ A, const float* __restrict__ A1, int strideA,
    const float* __restrict__ W,
    int bm, int bn, int k0, int Ncol, int tid)
{
    const float* Abase = A;
    int acol = k0;
    int astr = strideA;
    if (A1) {
        astr = 128;
        if (k0 >= 128) { Abase = A1; acol = k0 - 128; }
    }
#pragma unroll
    for (int i = 0; i < 4; i++) {
        int idx = tid + i * 256;
        int m = idx >> 3, kc = idx & 7;
        cp16((uint32_t)__cvta_generic_to_shared(&AS(s, m, kc * 4)),
             &Abase[(size_t)(bm + m) * astr + acol + kc * 4]);
    }
#pragma unroll
    for (int i = 0; i < 4; i++) {
        int idx = tid + i * 256;
        int kk = idx >> 5, nc = idx & 31;
        cp16((uint32_t)__cvta_generic_to_shared(&BS(s, kk, nc * 4)),
             &W[(size_t)(k0 + kk) * Ncol + bn + nc * 4]);
    }
    asm volatile("cp.async.commit_group;");
}

__device__ __forceinline__ void compute_stage(const float* smem, int s, Frag& f,
                                              int wm, int wn, int g, int tg)
{
#pragma unroll
    for (int ks = 0; ks < 4; ks++) {
        const int kb = ks * 8;
        uint32_t afr[4][4], bfr[4][2];
#pragma unroll
        for (int mt = 0; mt < 4; mt++) {
            int mr = wm + mt * 16 + g;
            afr[mt][0] = to_tf32(AS(s, mr,     kb + tg));
            afr[mt][1] = to_tf32(AS(s, mr + 8, kb + tg));
            afr[mt][2] = to_tf32(AS(s, mr,     kb + tg + 4));
            afr[mt][3] = to_tf32(AS(s, mr + 8, kb + tg + 4));
        }
#pragma unroll
        for (int nt = 0; nt < 4; nt++) {
            int nc = wn + nt * 8 + g;
            bfr[nt][0] = to_tf32(BS(s, kb + tg,     nc));
            bfr[nt][1] = to_tf32(BS(s, kb + tg + 4, nc));
        }
#pragma unroll
        for (int mt = 0; mt < 4; mt++)
#pragma unroll
            for (int nt = 0; nt < 4; nt++) {
                asm volatile(
                    "mma.sync.aligned.m16n8k8.row.col.f32.tf32.tf32.f32 "
                    "{%0,%1,%2,%3}, {%4,%5,%6,%7}, {%8,%9}, {%0,%1,%2,%3};"
                    : "+f"(f.c[mt][nt][0]), "+f"(f.c[mt][nt][1]),
                      "+f"(f.c[mt][nt][2]), "+f"(f.c[mt][nt][3])
                    : "r"(afr[mt][0]), "r"(afr[mt][1]),
                      "r"(afr[mt][2]), "r"(afr[mt][3]),
                      "r"(bfr[nt][0]), "r"(bfr[nt][1]));
            }
    }
}

// Pipelined GEMM; optional dual-A (concat rows) and dual-output (blockIdx.z selects W/bias/C).
__global__ __launch_bounds__(256) void gemm_pipe(
    const float* __restrict__ A, const float* __restrict__ A1,
    const float* __restrict__ W0, const float* __restrict__ W1,
    const float* __restrict__ b0, const float* __restrict__ b1,
    float* __restrict__ C0, float* __restrict__ C1,
    int M, int Ncol, int K)
{
    extern __shared__ float smem[];
    const int tid  = threadIdx.x;
    const int lane = tid & 31, warp = tid >> 5;
    const int g = lane >> 2, tg = lane & 3;
    const int wm = (warp >> 2) * 64, wn = (warp & 3) * 32;
    const int bm = blockIdx.y * TBM, bn = blockIdx.x * TBN;
    const int z  = blockIdx.z;
    const float* W    = z ? W1 : W0;
    const float* bias = z ? b1 : b0;
    float* C          = z ? C1 : C0;

    Frag f;
#pragma unroll
    for (int mt = 0; mt < 4; mt++)
#pragma unroll
        for (int nt = 0; nt < 4; nt++)
#pragma unroll
            for (int r = 0; r < 4; r++) f.c[mt][nt][r] = 0.f;

    const int KT = K / TBK;
    load_stage(smem, 0, A, A1, K, W, bm, bn, 0, Ncol, tid);
    for (int kt = 0; kt < KT; kt++) {
        int s = kt & 1;
        if (kt + 1 < KT) {
            load_stage(smem, s ^ 1, A, A1, K, W, bm, bn, (kt + 1) * TBK, Ncol, tid);
            asm volatile("cp.async.wait_group 1;");
        } else {
            asm volatile("cp.async.wait_group 0;");
        }
        __syncthreads();
        compute_stage(smem, s, f, wm, wn, g, tg);
        __syncthreads();
    }

#pragma unroll
    for (int mt = 0; mt < 4; mt++) {
        int r0 = bm + wm + mt * 16 + g;
#pragma unroll
        for (int nt = 0; nt < 4; nt++) {
            int col = bn + wn + nt * 8 + 2 * tg;
            float bb0 = bias ? bias[col] : 0.f;
            float bb1 = bias ? bias[col + 1] : 0.f;
            float2 v0 = make_float2(f.c[mt][nt][0] + bb0, f.c[mt][nt][1] + bb1);
            float2 v1 = make_float2(f.c[mt][nt][2] + bb0, f.c[mt][nt][3] + bb1);
            *(float2*)&C[(size_t)r0 * Ncol + col] = v0;
            *(float2*)&C[(size_t)(r0 + 8) * Ncol + col] = v1;
        }
    }
}

// gfeat GEMM with on-the-fly normalization of A:
// A[m][k] = num[m][k] / (den1[m][k>>6] + eps) + bias1[k];  C = A @ We2
__global__ __launch_bounds__(256) void gemm_gfeat(
    const float* __restrict__ num, const float* __restrict__ den,
    const float* __restrict__ bias1, const float* __restrict__ W,
    float* __restrict__ C)
{
    extern __shared__ float smem[];
    const int tid  = threadIdx.x;
    const int lane = tid & 31, warp = tid >> 5;
    const int g = lane >> 2, tg = lane & 3;
    const int wm = (warp >> 2) * 64, wn = (warp & 3) * 32;
    const int bm = blockIdx.y * TBM, bn = 0;
    const int Ncol = DED, K = DIN;

    Frag f;
#pragma unroll
    for (int mt = 0; mt < 4; mt++)
#pragma unroll
        for (int nt = 0; nt < 4; nt++)
#pragma unroll
            for (int r = 0; r < 4; r++) f.c[mt][nt][r] = 0.f;

    auto loadA = [&](int k0, float4* out) {
#pragma unroll
        for (int i = 0; i < 4; i++) {
            int idx = tid + i * 256;
            int m = idx >> 3, kc = idx & 7;
            int col = k0 + kc * 4;
            float4 v = *(const float4*)&num[(size_t)(bm + m) * DIN + col];
            float invd = __fdividef(1.f, den[(bm + m) * 4 + (col >> 6)] + EPSV);
            float4 b = *(const float4*)&bias1[col];
            out[i] = make_float4(v.x * invd + b.x, v.y * invd + b.y,
                                 v.z * invd + b.z, v.w * invd + b.w);
        }
    };
    auto stsA = [&](int s, const float4* regs) {
#pragma unroll
        for (int i = 0; i < 4; i++) {
            int idx = tid + i * 256;
            int m = idx >> 3, kc = idx & 7;
            *(float4*)&AS(s, m, kc * 4) = regs[i];
        }
    };
    auto loadB = [&](int s, int k0) {
#pragma unroll
        for (int i = 0; i < 4; i++) {
            int idx = tid + i * 256;
            int kk = idx >> 5, nc = idx & 31;
            cp16((uint32_t)__cvta_generic_to_shared(&BS(s, kk, nc * 4)),
                 &W[(size_t)(k0 + kk) * Ncol + bn + nc * 4]);
        }
        asm volatile("cp.async.commit_group;");
    };

    const int KT = K / TBK;
    float4 aregs[4];
    loadA(0, aregs);
    stsA(0, aregs);
    loadB(0, 0);
    for (int kt = 0; kt < KT; kt++) {
        int s = kt & 1;
        float4 anext[4];
        if (kt + 1 < KT) {
            loadA((kt + 1) * TBK, anext);
            loadB(s ^ 1, (kt + 1) * TBK);
            asm volatile("cp.async.wait_group 1;");
        } else {
            asm volatile("cp.async.wait_group 0;");
        }
        __syncthreads();
        compute_stage(smem, s, f, wm, wn, g, tg);
        __syncthreads();
        if (kt + 1 < KT) stsA(s ^ 1, anext);
    }

#pragma unroll
    for (int mt = 0; mt < 4; mt++) {
        int r0 = bm + wm + mt * 16 + g;
#pragma unroll
        for (int nt = 0; nt < 4; nt++) {
            int col = bn + wn + nt * 8 + 2 * tg;
            *(float2*)&C[(size_t)r0 * Ncol + col] =
                make_float2(f.c[mt][nt][0], f.c[mt][nt][1]);
            *(float2*)&C[(size_t)(r0 + 8) * Ncol + col] =
                make_float2(f.c[mt][nt][2], f.c[mt][nt][3]);
        }
    }
}

// Fused layer-1: e1 = trace @ We in smem, then per-edge logit -> exp ->
// numerator (ex * xl[src]) RED into g_num + denominator RED into den1.
// grid (2, E1/128). Phase-2: 8 edges at a time, front-batched gathers (MLP=16).
__global__ __launch_bounds__(256) void gemm_alpha1_agg1_fused(
    const float* __restrict__ A,      // x_trace [E1,128]
    const float* __restrict__ W,      // n2n_We [128,256]
    const int*   __restrict__ adj,    // node_adj [2,E1]
    const float* __restrict__ att)    // [4,64]
{
    extern __shared__ float smem[];
    const int tid  = threadIdx.x;
    const int lane = tid & 31, warp = tid >> 5;
    const int g = lane >> 2, tg = lane & 3;
    const int wm = (warp >> 2) * 64, wn = (warp & 3) * 32;
    const int bm = blockIdx.y * TBM, bn = blockIdx.x * TBN;
    const int K = 128, Ncol = DIN;

    Frag f;
#pragma unroll
    for (int mt = 0; mt < 4; mt++)
#pragma unroll
        for (int nt = 0; nt < 4; nt++)
#pragma unroll
            for (int r = 0; r < 4; r++) f.c[mt][nt][r] = 0.f;

    const int KT = K / TBK;
    load_stage(smem, 0, A, nullptr, K, W, bm, bn, 0, Ncol, tid);
    for (int kt = 0; kt < KT; kt++) {
        int s = kt & 1;
        if (kt + 1 < KT) {
            load_stage(smem, s ^ 1, A, nullptr, K, W, bm, bn, (kt + 1) * TBK, Ncol, tid);
            asm volatile("cp.async.wait_group 1;");
        } else {
            asm volatile("cp.async.wait_group 0;");
        }
        __syncthreads();
        compute_stage(smem, s, f, wm, wn, g, tg);
        __syncthreads();
    }

    // stage e1 tile into smem
#pragma unroll
    for (int mt = 0; mt < 4; mt++) {
        int r0 = wm + mt * 16 + g;
#pragma unroll
        for (int nt = 0; nt < 4; nt++) {
            int col = wn + nt * 8 + 2 * tg;
            ET(r0, col)         = f.c[mt][nt][0];
            ET(r0, col + 1)     = f.c[mt][nt][1];
            ET(r0 + 8, col)     = f.c[mt][nt][2];
            ET(r0 + 8, col + 1) = f.c[mt][nt][3];
        }
    }
    __syncthreads();

    // phase 2: 8 edges at a time, gathers front-batched
    const float4 av = *(const float4*)&att[bn + lane * 4];
#pragma unroll
    for (int it = 0; it < 2; it++) {
        int er = warp * 16 + it * 8;
        int eg = bm + er;
        int s_[8], d_[8];
#pragma unroll
        for (int i = 0; i < 8; i++) {
            s_[i] = adj[eg + i];
            d_[i] = adj[E1_ + eg + i];
        }
        float4 xlv[8], xrv[8];
#pragma unroll
        for (int i = 0; i < 8; i++) xlv[i] = *(const float4*)&g_xl[(size_t)s_[i] * DIN + bn + lane * 4];
#pragma unroll
        for (int i = 0; i < 8; i++) xrv[i] = *(const float4*)&g_xr[(size_t)d_[i] * DIN + bn + lane * 4];

        float p[8];
#pragma unroll
        for (int i = 0; i < 8; i++) {
            float q;
            q  = lrelu02(xlv[i].x + xrv[i].x + ET(er + i, lane * 4 + 0)) * av.x;
            q += lrelu02(xlv[i].y + xrv[i].y + ET(er + i, lane * 4 + 1)) * av.y;
            q += lrelu02(xlv[i].z + xrv[i].z + ET(er + i, lane * 4 + 2)) * av.z;
            q += lrelu02(xlv[i].w + xrv[i].w + ET(er + i, lane * 4 + 3)) * av.w;
            p[i] = q;
        }
#pragma unroll
        for (int off = 8; off > 0; off >>= 1) {
#pragma unroll
            for (int i = 0; i < 8; i++)
                p[i] += __shfl_xor_sync(0xffffffff, p[i], off);
        }
#pragma unroll
        for (int i = 0; i < 8; i++) {
            float ex = expf(p[i]);
            red_add_v4(&g_num[(size_t)d_[i] * DIN + bn + lane * 4],
                       make_float4(ex * xlv[i].x, ex * xlv[i].y, ex * xlv[i].z, ex * xlv[i].w));
            if (lane == 0 || lane == 16) {
                int head = 2 * blockIdx.x + (lane >> 4);
                atomicAdd(&g_den1[(size_t)d_[i] * 4 + head], ex);
            }
        }
    }
}

// ---------------- prep: zero numerator + den inits ----------------
__global__ void prep_kernel() {
    size_t idx = (size_t)blockIdx.x * blockDim.x + threadIdx.x;
    if (idx >= (size_t)NN_ * DIN / 4) return;
    ((float4*)g_num)[idx] = make_float4(0.f, 0.f, 0.f, 0.f);
    if (idx < NN_ * 4) g_den1[idx] = 0.f;
    if (idx < (size_t)E1_ * 4) g_den2[idx] = 0.f;
}

// write xn / xlg output regions from numerator (float4, runs on side stream)
__global__ void write_node_out_kernel(float* __restrict__ out, const float* __restrict__ bias1) {
    size_t idx = (size_t)blockIdx.x * blockDim.x + threadIdx.x;
    if (idx >= (size_t)NN_ * 64) return;
    int i = (int)(idx >> 6), c4 = (int)(idx & 63) * 4;
    float4 v = *(const float4*)&g_num[(size_t)i * DIN + c4];
    float invd = __fdividef(1.f, g_den1[i * 4 + (c4 >> 6)] + EPSV);
    float4 b = *(const float4*)&bias1[c4];
    float4 r = make_float4(v.x * invd + b.x, v.y * invd + b.y,
                           v.z * invd + b.z, v.w * invd + b.w);
    const size_t XN = (size_t)NN_ * 128;
    const size_t XT = (size_t)E1_ * 128;
    if (c4 < 128) *(float4*)&out[(size_t)i * 128 + c4] = r;
    else          *(float4*)&out[XN + XT + (size_t)i * 128 + (c4 - 128)] = r;
}

// ---------------- layer-2 merged attention + aggregate, 8 edges/warp ----------------
// All 24 row gathers issued before any compute (MLP=24), then per-edge exp + RED.
__global__ __launch_bounds__(256) void alpha2_agg2_kernel(const int* __restrict__ adj,
                                                          const int* __restrict__ efea,
                                                          const float* __restrict__ att,
                                                          float* __restrict__ out_xt)
{
    int warp = (blockIdx.x * blockDim.x + threadIdx.x) >> 5;
    int lane = threadIdx.x & 31;
    int e0 = warp * 8;
    if (e0 >= E2_) return;
    float4 av = *(const float4*)&att[lane * 4];

    int src[8], dst[8], ef[8];
#pragma unroll
    for (int i = 0; i < 8; i++) {
        src[i] = adj[e0 + i];
        dst[i] = adj[(size_t)E2_ + e0 + i];
        ef[i]  = efea[e0 + i];
    }

    float4 xl[8], xr[8], ee[8];
#pragma unroll
    for (int i = 0; i < 8; i++) xl[i] = *(const float4*)&g_xl2  [(size_t)src[i] * DED + lane * 4];
#pragma unroll
    for (int i = 0; i < 8; i++) xr[i] = *(const float4*)&g_xr2  [(size_t)dst[i] * DED + lane * 4];
#pragma unroll
    for (int i = 0; i < 8; i++) ee[i] = *(const float4*)&g_gfeat[(size_t)ef[i]  * DED + lane * 4];

    float p[8];
#pragma unroll
    for (int i = 0; i < 8; i++) {
        float q;
        q  = lrelu02(xl[i].x + xr[i].x + ee[i].x) * av.x;
        q += lrelu02(xl[i].y + xr[i].y + ee[i].y) * av.y;
        q += lrelu02(xl[i].z + xr[i].z + ee[i].z) * av.z;
        q += lrelu02(xl[i].w + xr[i].w + ee[i].w) * av.w;
        p[i] = q;
    }
#pragma unroll
    for (int off = 4; off > 0; off >>= 1) {
#pragma unroll
        for (int i = 0; i < 8; i++)
            p[i] += __shfl_xor_sync(0xffffffff, p[i], off);
    }
#pragma unroll
    for (int i = 0; i < 8; i++) {
        float ex = expf(p[i]);
        red_add_v4(&out_xt[(size_t)dst[i] * DED + lane * 4],
                   make_float4(ex * xl[i].x, ex * xl[i].y, ex * xl[i].z, ex * xl[i].w));
        if ((lane & 7) == 0)
            atomicAdd(&g_den2[(size_t)dst[i] * 4 + (lane >> 3)], ex);
    }
}

// seed xt output region with zeros (float4)
__global__ void seed_xt_kernel(float* __restrict__ out_xt) {
    size_t idx = (size_t)blockIdx.x * blockDim.x + threadIdx.x;
    if (idx >= (size_t)E1_ * 32) return;
    ((float4*)out_xt)[idx] = make_float4(0.f, 0.f, 0.f, 0.f);
}

// normalize xt in place (float4): divide by den, add bias
__global__ void normalize_xt_kernel(float* __restrict__ out_xt, const float* __restrict__ bias2) {
    size_t idx = (size_t)blockIdx.x * blockDim.x + threadIdx.x;
    if (idx >= (size_t)E1_ * 32) return;
    int e = (int)(idx >> 5), c4 = (int)(idx & 31) * 4;
    float4 v = ((const float4*)out_xt)[idx];
    float invd = __fdividef(1.f, g_den2[(size_t)e * 4 + (c4 >> 5)] + EPSV);
    float4 b = *(const float4*)&bias2[c4];
    ((float4*)out_xt)[idx] = make_float4(v.x * invd + b.x, v.y * invd + b.y,
                                         v.z * invd + b.z, v.w * invd + b.w);
}

// ---------------- launch ----------------
extern "C" void kernel_launch(void* const* d_in, const int* in_sizes, int n_in,
                              void* d_out, int out_size)
{
    const float* x_node   = (const float*)d_in[0];
    const float* x_trace  = (const float*)d_in[1];
    const float* x_log    = (const float*)d_in[2];
    const int*   node_adj = (const int*)d_in[3];
    const int*   edge_adj = (const int*)d_in[4];
    const int*   edge_efea= (const int*)d_in[5];
    const float* n2n_Wl   = (const float*)d_in[6];
    const float* n2n_bl   = (const float*)d_in[7];
    const float* n2n_Wr   = (const float*)d_in[8];
    const float* n2n_br   = (const float*)d_in[9];
    const float* n2n_We   = (const float*)d_in[10];
    const float* n2n_att  = (const float*)d_in[11];
    const float* n2n_bias = (const float*)d_in[12];
    const float* e2n_Wl   = (const float*)d_in[13];
    const float* e2n_bl   = (const float*)d_in[14];
    const float* e2n_Wr   = (const float*)d_in[15];
    const float* e2n_br   = (const float*)d_in[16];
    const float* e2n_We   = (const float*)d_in[17];
    const float* e2n_att  = (const float*)d_in[18];
    const float* e2n_bias = (const float*)d_in[19];
    float* out = (float*)d_out;
    float* out_xt = out + (size_t)NN_ * 128;

    float* p_xl;   cudaGetSymbolAddress((void**)&p_xl,   g_xl);
    float* p_xr;   cudaGetSymbolAddress((void**)&p_xr,   g_xr);
    float* p_num;  cudaGetSymbolAddress((void**)&p_num,  g_num);
    float* p_den1; cudaGetSymbolAddress((void**)&p_den1, g_den1);
    float* p_xl2;  cudaGetSymbolAddress((void**)&p_xl2,  g_xl2);
    float* p_xr2;  cudaGetSymbolAddress((void**)&p_xr2,  g_xr2);
    float* p_g;    cudaGetSymbolAddress((void**)&p_g,    g_gfeat);

    const int SMEM_PIPE = 2 * STG * 4;
    static cudaStream_t s1 = nullptr;
    static cudaEvent_t evA = nullptr, evB = nullptr, evP = nullptr, evC = nullptr, evD = nullptr;
    if (!s1) {
        cudaFuncSetAttribute(gemm_pipe, cudaFuncAttributeMaxDynamicSharedMemorySize, SMEM_PIPE);
        cudaFuncSetAttribute(gemm_gfeat, cudaFuncAttributeMaxDynamicSharedMemorySize, SMEM_PIPE);
        cudaFuncSetAttribute(gemm_alpha1_agg1_fused, cudaFuncAttributeMaxDynamicSharedMemorySize, SMEM_PIPE);
        cudaStreamCreateWithFlags(&s1, cudaStreamNonBlocking);
        cudaEventCreateWithFlags(&evA, cudaEventDisableTiming);
        cudaEventCreateWithFlags(&evB, cudaEventDisableTiming);
        cudaEventCreateWithFlags(&evP, cudaEventDisableTiming);
        cudaEventCreateWithFlags(&evC, cudaEventDisableTiming);
        cudaEventCreateWithFlags(&evD, cudaEventDisableTiming);
    }

    // fork side stream: prep + zero-seed xt + xl2/xr2 GEMM
    cudaEventRecord(evA, 0);
    cudaStreamWaitEvent(s1, evA, 0);
    prep_kernel<<<(NN_ * DIN / 4 + 255) / 256, 256, 0, s1>>>();
    cudaEventRecord(evP, s1);
    seed_xt_kernel<<<(E1_ * 32) / 256, 256, 0, s1>>>(out_xt);
    {
        dim3 gdim(DED / TBN, E1_ / TBM, 2);
        gemm_pipe<<<gdim, 256, SMEM_PIPE, s1>>>(x_trace, nullptr, e2n_Wl, e2n_Wr, e2n_bl, e2n_br,
                                                p_xl2, p_xr2, E1_, DED, DED);
    }
    cudaEventRecord(evB, s1);

    // main stream: xl/xr (dual-A, no concat) -> (wait prep) -> fused alpha1+agg1
    {
        dim3 gdim(DIN / TBN, NN_ / TBM, 2);
        gemm_pipe<<<gdim, 256, SMEM_PIPE>>>(x_node, x_log, n2n_Wl, n2n_Wr, n2n_bl, n2n_br,
                                            p_xl, p_xr, NN_, DIN, DIN);
    }
    cudaStreamWaitEvent(0, evP, 0);
    {
        dim3 gdim(DIN / TBN, E1_ / TBM);
        gemm_alpha1_agg1_fused<<<gdim, 256, SMEM_PIPE>>>(x_trace, n2n_We, node_adj, n2n_att);
    }
    cudaEventRecord(evC, 0);   // numerator + den1 final

    // side stream: write xn/xlg outputs while main does gfeat + alpha2_agg2
    cudaStreamWaitEvent(s1, evC, 0);
    write_node_out_kernel<<<(NN_ * 64) / 256, 256, 0, s1>>>(out, n2n_bias);
    cudaEventRecord(evD, s1);

    // main: gfeat = normalize(num) @ We2
    {
        dim3 gdim(1, NN_ / TBM);
        gemm_gfeat<<<gdim, 256, SMEM_PIPE>>>(p_num, p_den1, n2n_bias, e2n_We, p_g);
    }

    // join: merged layer-2 needs xl2/xr2 + seeded xt from side stream
    cudaStreamWaitEvent(0, evB, 0);

    alpha2_agg2_kernel<<<E2_ / 64, 256>>>(edge_adj, edge_efea, e2n_att, out_xt);
    normalize_xt_kernel<<<(E1_ * 32) / 256, 256>>>(out_xt, e2n_bias);

    // final join: node-out writes ordered into stream 0
    cudaStreamWaitEvent(0, evD, 0);
}

// round 17
// speedup vs baseline: 1.0312x; 1.0312x over previous
#include <cuda_runtime.h>
#include <stdint.h>
#include <math.h>
#include <float.h>

// ---------------- problem constants ----------------
#define NN_   8192      // nodes
#define E1_   131072    // node-graph edges (= trace rows)
#define E2_   524288    // line-graph edges
#define DIN   256       // layer1 channels (4 heads x 64)
#define DED   128       // layer2 channels (4 heads x 32)
#define EPSV  1e-16f

// ---------------- scratch (static device, no allocs) ----------------
__device__ float g_xl     [(size_t)NN_ * DIN];
__device__ float g_xr     [(size_t)NN_ * DIN];
__device__ float g_den1   [(size_t)NN_ * 4];
__device__ float g_num    [(size_t)NN_ * DIN];  // layer-1 numerator
__device__ float g_xl2    [(size_t)E1_ * DED];
__device__ float g_xr2    [(size_t)E1_ * DED];
__device__ float g_gfeat  [(size_t)NN_ * DED];
__device__ float g_den2   [(size_t)E1_ * 4];

// ---------------- helpers ----------------
__device__ __forceinline__ float lrelu02(float x) { return x > 0.f ? x : 0.2f * x; }
__device__ __forceinline__ uint32_t to_tf32(float v) {
    uint32_t t;
    asm("cvt.rna.tf32.f32 %0, %1;" : "=r"(t) : "f"(v));
    return t;
}
__device__ __forceinline__ void cp16(uint32_t dst, const void* src) {
    asm volatile("cp.async.cg.shared.global [%0], [%1], 16;" :: "r"(dst), "l"(src));
}
__device__ __forceinline__ void red_add_v4(float* addr, float4 v) {
    asm volatile("red.global.add.v4.f32 [%0], {%1,%2,%3,%4};"
                 :: "l"(addr), "f"(v.x), "f"(v.y), "f"(v.z), "f"(v.w) : "memory");
}

// ---------------- tf32 GEMM tiles ----------------
#define TBM 128
#define TBN 128
#define TBK 32
#define STG 8960                 // floats per stage: 128*36 + 32*136
#define AS(S,M,K_) smem[(S)*STG + (M)*36 + (K_)]
#define BS(S,KK,N_) smem[(S)*STG + 4608 + (KK)*136 + (N_)]
#define ET(R,C) smem[(R)*132 + (C)]

struct Frag { float c[4][4][4]; };

// A source: if A1 != nullptr, rows come from A (k<128) or A1 (k>=128), each stride 128.
__device__ __forceinline__ void load_stage(float* smem, int s,
    const float* __restrict__ A, const float* __restrict__ A1, int strideA,
    const float* __restrict__ W,
    int bm, int bn, int k0, int Ncol, int tid)
{
    const float* Abase = A;
    int acol = k0;
    int astr = strideA;
    if (A1) {
        astr = 128;
        if (k0 >= 128) { Abase = A1; acol = k0 - 128; }
    }
#pragma unroll
    for (int i = 0; i < 4; i++) {
        int idx = tid + i * 256;
        int m = idx >> 3, kc = idx & 7;
        cp16((uint32_t)__cvta_generic_to_shared(&AS(s, m, kc * 4)),
             &Abase[(size_t)(bm + m) * astr + acol + kc * 4]);
    }
#pragma unroll
    for (int i = 0; i < 4; i++) {
        int idx = tid + i * 256;
        int kk = idx >> 5, nc = idx & 31;
        cp16((uint32_t)__cvta_generic_to_shared(&BS(s, kk, nc * 4)),
             &W[(size_t)(k0 + kk) * Ncol + bn + nc * 4]);
    }
    asm volatile("cp.async.commit_group;");
}

__device__ __forceinline__ void compute_stage(const float* smem, int s, Frag& f,
                                              int wm, int wn, int g, int tg)
{
#pragma unroll
    for (int ks = 0; ks < 4; ks++) {
        const int kb = ks * 8;
        uint32_t afr[4][4], bfr[4][2];
#pragma unroll
        for (int mt = 0; mt < 4; mt++) {
            int mr = wm + mt * 16 + g;
            afr[mt][0] = to_tf32(AS(s, mr,     kb + tg));
            afr[mt][1] = to_tf32(AS(s, mr + 8, kb + tg));
            afr[mt][2] = to_tf32(AS(s, mr,     kb + tg + 4));
            afr[mt][3] = to_tf32(AS(s, mr + 8, kb + tg + 4));
        }
#pragma unroll
        for (int nt = 0; nt < 4; nt++) {
            int nc = wn + nt * 8 + g;
            bfr[nt][0] = to_tf32(BS(s, kb + tg,     nc));
            bfr[nt][1] = to_tf32(BS(s, kb + tg + 4, nc));
        }
#pragma unroll
        for (int mt = 0; mt < 4; mt++)
#pragma unroll
            for (int nt = 0; nt < 4; nt++) {
                asm volatile(
                    "mma.sync.aligned.m16n8k8.row.col.f32.tf32.tf32.f32 "
                    "{%0,%1,%2,%3}, {%4,%5,%6,%7}, {%8,%9}, {%0,%1,%2,%3};"
                    : "+f"(f.c[mt][nt][0]), "+f"(f.c[mt][nt][1]),
                      "+f"(f.c[mt][nt][2]), "+f"(f.c[mt][nt][3])
                    : "r"(afr[mt][0]), "r"(afr[mt][1]),
                      "r"(afr[mt][2]), "r"(afr[mt][3]),
                      "r"(bfr[nt][0]), "r"(bfr[nt][1]));
            }
    }
}

// Pipelined GEMM; optional dual-A (concat rows) and dual-output (blockIdx.z selects W/bias/C).
__global__ __launch_bounds__(256) void gemm_pipe(
    const float* __restrict__ A, const float* __restrict__ A1,
    const float* __restrict__ W0, const float* __restrict__ W1,
    const float* __restrict__ b0, const float* __restrict__ b1,
    float* __restrict__ C0, float* __restrict__ C1,
    int M, int Ncol, int K)
{
    extern __shared__ float smem[];
    const int tid  = threadIdx.x;
    const int lane = tid & 31, warp = tid >> 5;
    const int g = lane >> 2, tg = lane & 3;
    const int wm = (warp >> 2) * 64, wn = (warp & 3) * 32;
    const int bm = blockIdx.y * TBM, bn = blockIdx.x * TBN;
    const int z  = blockIdx.z;
    const float* W    = z ? W1 : W0;
    const float* bias = z ? b1 : b0;
    float* C          = z ? C1 : C0;

    Frag f;
#pragma unroll
    for (int mt = 0; mt < 4; mt++)
#pragma unroll
        for (int nt = 0; nt < 4; nt++)
#pragma unroll
            for (int r = 0; r < 4; r++) f.c[mt][nt][r] = 0.f;

    const int KT = K / TBK;
    load_stage(smem, 0, A, A1, K, W, bm, bn, 0, Ncol, tid);
    for (int kt = 0; kt < KT; kt++) {
        int s = kt & 1;
        if (kt + 1 < KT) {
            load_stage(smem, s ^ 1, A, A1, K, W, bm, bn, (kt + 1) * TBK, Ncol, tid);
            asm volatile("cp.async.wait_group 1;");
        } else {
            asm volatile("cp.async.wait_group 0;");
        }
        __syncthreads();
        compute_stage(smem, s, f, wm, wn, g, tg);
        __syncthreads();
    }

#pragma unroll
    for (int mt = 0; mt < 4; mt++) {
        int r0 = bm + wm + mt * 16 + g;
#pragma unroll
        for (int nt = 0; nt < 4; nt++) {
            int col = bn + wn + nt * 8 + 2 * tg;
            float bb0 = bias ? bias[col] : 0.f;
            float bb1 = bias ? bias[col + 1] : 0.f;
            float2 v0 = make_float2(f.c[mt][nt][0] + bb0, f.c[mt][nt][1] + bb1);
            float2 v1 = make_float2(f.c[mt][nt][2] + bb0, f.c[mt][nt][3] + bb1);
            *(float2*)&C[(size_t)r0 * Ncol + col] = v0;
            *(float2*)&C[(size_t)(r0 + 8) * Ncol + col] = v1;
        }
    }
}

// gfeat GEMM with on-the-fly normalization of A:
// A[m][k] = num[m][k] / (den1[m][k>>6] + eps) + bias1[k];  C = A @ We2
__global__ __launch_bounds__(256) void gemm_gfeat(
    const float* __restrict__ num, const float* __restrict__ den,
    const float* __restrict__ bias1, const float* __restrict__ W,
    float* __restrict__ C)
{
    extern __shared__ float smem[];
    const int tid  = threadIdx.x;
    const int lane = tid & 31, warp = tid >> 5;
    const int g = lane >> 2, tg = lane & 3;
    const int wm = (warp >> 2) * 64, wn = (warp & 3) * 32;
    const int bm = blockIdx.y * TBM, bn = 0;
    const int Ncol = DED, K = DIN;

    Frag f;
#pragma unroll
    for (int mt = 0; mt < 4; mt++)
#pragma unroll
        for (int nt = 0; nt < 4; nt++)
#pragma unroll
            for (int r = 0; r < 4; r++) f.c[mt][nt][r] = 0.f;

    auto loadA = [&](int k0, float4* out) {
#pragma unroll
        for (int i = 0; i < 4; i++) {
            int idx = tid + i * 256;
            int m = idx >> 3, kc = idx & 7;
            int col = k0 + kc * 4;
            float4 v = *(const float4*)&num[(size_t)(bm + m) * DIN + col];
            float invd = __fdividef(1.f, den[(bm + m) * 4 + (col >> 6)] + EPSV);
            float4 b = *(const float4*)&bias1[col];
            out[i] = make_float4(v.x * invd + b.x, v.y * invd + b.y,
                                 v.z * invd + b.z, v.w * invd + b.w);
        }
    };
    auto stsA = [&](int s, const float4* regs) {
#pragma unroll
        for (int i = 0; i < 4; i++) {
            int idx = tid + i * 256;
            int m = idx >> 3, kc = idx & 7;
            *(float4*)&AS(s, m, kc * 4) = regs[i];
        }
    };
    auto loadB = [&](int s, int k0) {
#pragma unroll
        for (int i = 0; i < 4; i++) {
            int idx = tid + i * 256;
            int kk = idx >> 5, nc = idx & 31;
            cp16((uint32_t)__cvta_generic_to_shared(&BS(s, kk, nc * 4)),
                 &W[(size_t)(k0 + kk) * Ncol + bn + nc * 4]);
        }
        asm volatile("cp.async.commit_group;");
    };

    const int KT = K / TBK;
    float4 aregs[4];
    loadA(0, aregs);
    stsA(0, aregs);
    loadB(0, 0);
    for (int kt = 0; kt < KT; kt++) {
        int s = kt & 1;
        float4 anext[4];
        if (kt + 1 < KT) {
            loadA((kt + 1) * TBK, anext);
            loadB(s ^ 1, (kt + 1) * TBK);
            asm volatile("cp.async.wait_group 1;");
        } else {
            asm volatile("cp.async.wait_group 0;");
        }
        __syncthreads();
        compute_stage(smem, s, f, wm, wn, g, tg);
        __syncthreads();
        if (kt + 1 < KT) stsA(s ^ 1, anext);
    }

#pragma unroll
    for (int mt = 0; mt < 4; mt++) {
        int r0 = bm + wm + mt * 16 + g;
#pragma unroll
        for (int nt = 0; nt < 4; nt++) {
            int col = bn + wn + nt * 8 + 2 * tg;
            *(float2*)&C[(size_t)r0 * Ncol + col] =
                make_float2(f.c[mt][nt][0], f.c[mt][nt][1]);
            *(float2*)&C[(size_t)(r0 + 8) * Ncol + col] =
                make_float2(f.c[mt][nt][2], f.c[mt][nt][3]);
        }
    }
}

// Fused layer-1: e1 = trace @ We in smem, then per-edge logit -> exp ->
// numerator (ex * xl[src]) RED into g_num + denominator RED into den1.
// grid (2, E1/128). Phase-2: 8 edges at a time, int4 index loads, front-batched gathers.
__global__ __launch_bounds__(256) void gemm_alpha1_agg1_fused(
    const float* __restrict__ A,      // x_trace [E1,128]
    const float* __restrict__ W,      // n2n_We [128,256]
    const int*   __restrict__ adj,    // node_adj [2,E1]
    const float* __restrict__ att)    // [4,64]
{
    extern __shared__ float smem[];
    const int tid  = threadIdx.x;
    const int lane = tid & 31, warp = tid >> 5;
    const int g = lane >> 2, tg = lane & 3;
    const int wm = (warp >> 2) * 64, wn = (warp & 3) * 32;
    const int bm = blockIdx.y * TBM, bn = blockIdx.x * TBN;
    const int K = 128, Ncol = DIN;

    Frag f;
#pragma unroll
    for (int mt = 0; mt < 4; mt++)
#pragma unroll
        for (int nt = 0; nt < 4; nt++)
#pragma unroll
            for (int r = 0; r < 4; r++) f.c[mt][nt][r] = 0.f;

    const int KT = K / TBK;
    load_stage(smem, 0, A, nullptr, K, W, bm, bn, 0, Ncol, tid);
    for (int kt = 0; kt < KT; kt++) {
        int s = kt & 1;
        if (kt + 1 < KT) {
            load_stage(smem, s ^ 1, A, nullptr, K, W, bm, bn, (kt + 1) * TBK, Ncol, tid);
            asm volatile("cp.async.wait_group 1;");
        } else {
            asm volatile("cp.async.wait_group 0;");
        }
        __syncthreads();
        compute_stage(smem, s, f, wm, wn, g, tg);
        __syncthreads();
    }

    // stage e1 tile into smem
#pragma unroll
    for (int mt = 0; mt < 4; mt++) {
        int r0 = wm + mt * 16 + g;
#pragma unroll
        for (int nt = 0; nt < 4; nt++) {
            int col = wn + nt * 8 + 2 * tg;
            ET(r0, col)         = f.c[mt][nt][0];
            ET(r0, col + 1)     = f.c[mt][nt][1];
            ET(r0 + 8, col)     = f.c[mt][nt][2];
            ET(r0 + 8, col + 1) = f.c[mt][nt][3];
        }
    }
    __syncthreads();

    // phase 2: 8 edges at a time, int4 index loads, gathers front-batched
    const float4 av = *(const float4*)&att[bn + lane * 4];
#pragma unroll
    for (int it = 0; it < 2; it++) {
        int er = warp * 16 + it * 8;
        int eg = bm + er;
        int4 sa = *(const int4*)&adj[eg];
        int4 sb = *(const int4*)&adj[eg + 4];
        int4 da = *(const int4*)&adj[E1_ + eg];
        int4 db = *(const int4*)&adj[E1_ + eg + 4];
        int s_[8] = { sa.x, sa.y, sa.z, sa.w, sb.x, sb.y, sb.z, sb.w };
        int d_[8] = { da.x, da.y, da.z, da.w, db.x, db.y, db.z, db.w };

        float4 xlv[8], xrv[8];
#pragma unroll
        for (int i = 0; i < 8; i++) xlv[i] = *(const float4*)&g_xl[(size_t)s_[i] * DIN + bn + lane * 4];
#pragma unroll
        for (int i = 0; i < 8; i++) xrv[i] = *(const float4*)&g_xr[(size_t)d_[i] * DIN + bn + lane * 4];

        float p[8];
#pragma unroll
        for (int i = 0; i < 8; i++) {
            float q;
            q  = lrelu02(xlv[i].x + xrv[i].x + ET(er + i, lane * 4 + 0)) * av.x;
            q += lrelu02(xlv[i].y + xrv[i].y + ET(er + i, lane * 4 + 1)) * av.y;
            q += lrelu02(xlv[i].z + xrv[i].z + ET(er + i, lane * 4 + 2)) * av.z;
            q += lrelu02(xlv[i].w + xrv[i].w + ET(er + i, lane * 4 + 3)) * av.w;
            p[i] = q;
        }
#pragma unroll
        for (int off = 8; off > 0; off >>= 1) {
#pragma unroll
            for (int i = 0; i < 8; i++)
                p[i] += __shfl_xor_sync(0xffffffff, p[i], off);
        }
#pragma unroll
        for (int i = 0; i < 8; i++) {
            float ex = expf(p[i]);
            red_add_v4(&g_num[(size_t)d_[i] * DIN + bn + lane * 4],
                       make_float4(ex * xlv[i].x, ex * xlv[i].y, ex * xlv[i].z, ex * xlv[i].w));
            if (lane == 0 || lane == 16) {
                int head = 2 * blockIdx.x + (lane >> 4);
                atomicAdd(&g_den1[(size_t)d_[i] * 4 + head], ex);
            }
        }
    }
}

// ---------------- prep: zero numerator + den inits ----------------
__global__ void prep_kernel() {
    size_t idx = (size_t)blockIdx.x * blockDim.x + threadIdx.x;
    if (idx >= (size_t)NN_ * DIN / 4) return;
    ((float4*)g_num)[idx] = make_float4(0.f, 0.f, 0.f, 0.f);
    if (idx < NN_ * 4) g_den1[idx] = 0.f;
    if (idx < (size_t)E1_ * 4) g_den2[idx] = 0.f;
}

// write xn / xlg output regions from numerator (float4, runs on side stream)
__global__ void write_node_out_kernel(float* __restrict__ out, const float* __restrict__ bias1) {
    size_t idx = (size_t)blockIdx.x * blockDim.x + threadIdx.x;
    if (idx >= (size_t)NN_ * 64) return;
    int i = (int)(idx >> 6), c4 = (int)(idx & 63) * 4;
    float4 v = *(const float4*)&g_num[(size_t)i * DIN + c4];
    float invd = __fdividef(1.f, g_den1[i * 4 + (c4 >> 6)] + EPSV);
    float4 b = *(const float4*)&bias1[c4];
    float4 r = make_float4(v.x * invd + b.x, v.y * invd + b.y,
                           v.z * invd + b.z, v.w * invd + b.w);
    const size_t XN = (size_t)NN_ * 128;
    const size_t XT = (size_t)E1_ * 128;
    if (c4 < 128) *(float4*)&out[(size_t)i * 128 + c4] = r;
    else          *(float4*)&out[XN + XT + (size_t)i * 128 + (c4 - 128)] = r;
}

// ---------------- layer-2 merged attention + aggregate, 4 edges/warp ----------------
// int4 index loads; all 12 row gathers front-batched (MLP=12).
__global__ __launch_bounds__(256) void alpha2_agg2_kernel(const int* __restrict__ adj,
                                                          const int* __restrict__ efea,
                                                          const float* __restrict__ att,
                                                          float* __restrict__ out_xt)
{
    int warp = (blockIdx.x * blockDim.x + threadIdx.x) >> 5;
    int lane = threadIdx.x & 31;
    int e0 = warp * 4;
    if (e0 >= E2_) return;
    float4 av = *(const float4*)&att[lane * 4];

    int4 sv = *(const int4*)&adj[e0];
    int4 dv = *(const int4*)&adj[(size_t)E2_ + e0];
    int4 ev = *(const int4*)&efea[e0];
    int src[4] = { sv.x, sv.y, sv.z, sv.w };
    int dst[4] = { dv.x, dv.y, dv.z, dv.w };
    int ef[4]  = { ev.x, ev.y, ev.z, ev.w };

    float4 xl[4], xr[4], ee[4];
#pragma unroll
    for (int i = 0; i < 4; i++) xl[i] = *(const float4*)&g_xl2  [(size_t)src[i] * DED + lane * 4];
#pragma unroll
    for (int i = 0; i < 4; i++) xr[i] = *(const float4*)&g_xr2  [(size_t)dst[i] * DED + lane * 4];
#pragma unroll
    for (int i = 0; i < 4; i++) ee[i] = *(const float4*)&g_gfeat[(size_t)ef[i]  * DED + lane * 4];

    float p[4];
#pragma unroll
    for (int i = 0; i < 4; i++) {
        float q;
        q  = lrelu02(xl[i].x + xr[i].x + ee[i].x) * av.x;
        q += lrelu02(xl[i].y + xr[i].y + ee[i].y) * av.y;
        q += lrelu02(xl[i].z + xr[i].z + ee[i].z) * av.z;
        q += lrelu02(xl[i].w + xr[i].w + ee[i].w) * av.w;
        p[i] = q;
    }
#pragma unroll
    for (int off = 4; off > 0; off >>= 1) {
#pragma unroll
        for (int i = 0; i < 4; i++)
            p[i] += __shfl_xor_sync(0xffffffff, p[i], off);
    }
#pragma unroll
    for (int i = 0; i < 4; i++) {
        float ex = expf(p[i]);
        red_add_v4(&out_xt[(size_t)dst[i] * DED + lane * 4],
                   make_float4(ex * xl[i].x, ex * xl[i].y, ex * xl[i].z, ex * xl[i].w));
        if ((lane & 7) == 0)
            atomicAdd(&g_den2[(size_t)dst[i] * 4 + (lane >> 3)], ex);
    }
}

// seed xt output region with zeros (float4)
__global__ void seed_xt_kernel(float* __restrict__ out_xt) {
    size_t idx = (size_t)blockIdx.x * blockDim.x + threadIdx.x;
    if (idx >= (size_t)E1_ * 32) return;
    ((float4*)out_xt)[idx] = make_float4(0.f, 0.f, 0.f, 0.f);
}

// normalize xt in place (float4): divide by den, add bias
__global__ void normalize_xt_kernel(float* __restrict__ out_xt, const float* __restrict__ bias2) {
    size_t idx = (size_t)blockIdx.x * blockDim.x + threadIdx.x;
    if (idx >= (size_t)E1_ * 32) return;
    int e = (int)(idx >> 5), c4 = (int)(idx & 31) * 4;
    float4 v = ((const float4*)out_xt)[idx];
    float invd = __fdividef(1.f, g_den2[(size_t)e * 4 + (c4 >> 5)] + EPSV);
    float4 b = *(const float4*)&bias2[c4];
    ((float4*)out_xt)[idx] = make_float4(v.x * invd + b.x, v.y * invd + b.y,
                                         v.z * invd + b.z, v.w * invd + b.w);
}

// ---------------- launch ----------------
extern "C" void kernel_launch(void* const* d_in, const int* in_sizes, int n_in,
                              void* d_out, int out_size)
{
    const float* x_node   = (const float*)d_in[0];
    const float* x_trace  = (const float*)d_in[1];
    const float* x_log    = (const float*)d_in[2];
    const int*   node_adj = (const int*)d_in[3];
    const int*   edge_adj = (const int*)d_in[4];
    const int*   edge_efea= (const int*)d_in[5];
    const float* n2n_Wl   = (const float*)d_in[6];
    const float* n2n_bl   = (const float*)d_in[7];
    const float* n2n_Wr   = (const float*)d_in[8];
    const float* n2n_br   = (const float*)d_in[9];
    const float* n2n_We   = (const float*)d_in[10];
    const float* n2n_att  = (const float*)d_in[11];
    const float* n2n_bias = (const float*)d_in[12];
    const float* e2n_Wl   = (const float*)d_in[13];
    const float* e2n_bl   = (const float*)d_in[14];
    const float* e2n_Wr   = (const float*)d_in[15];
    const float* e2n_br   = (const float*)d_in[16];
    const float* e2n_We   = (const float*)d_in[17];
    const float* e2n_att  = (const float*)d_in[18];
    const float* e2n_bias = (const float*)d_in[19];
    float* out = (float*)d_out;
    float* out_xt = out + (size_t)NN_ * 128;

    float* p_xl;   cudaGetSymbolAddress((void**)&p_xl,   g_xl);
    float* p_xr;   cudaGetSymbolAddress((void**)&p_xr,   g_xr);
    float* p_num;  cudaGetSymbolAddress((void**)&p_num,  g_num);
    float* p_den1; cudaGetSymbolAddress((void**)&p_den1, g_den1);
    float* p_xl2;  cudaGetSymbolAddress((void**)&p_xl2,  g_xl2);
    float* p_xr2;  cudaGetSymbolAddress((void**)&p_xr2,  g_xr2);
    float* p_g;    cudaGetSymbolAddress((void**)&p_g,    g_gfeat);

    const int SMEM_PIPE = 2 * STG * 4;
    static cudaStream_t s1 = nullptr;
    static cudaEvent_t evA = nullptr, evB = nullptr, evP = nullptr, evC = nullptr, evD = nullptr;
    if (!s1) {
        cudaFuncSetAttribute(gemm_pipe, cudaFuncAttributeMaxDynamicSharedMemorySize, SMEM_PIPE);
        cudaFuncSetAttribute(gemm_gfeat, cudaFuncAttributeMaxDynamicSharedMemorySize, SMEM_PIPE);
        cudaFuncSetAttribute(gemm_alpha1_agg1_fused, cudaFuncAttributeMaxDynamicSharedMemorySize, SMEM_PIPE);
        cudaStreamCreateWithFlags(&s1, cudaStreamNonBlocking);
        cudaEventCreateWithFlags(&evA, cudaEventDisableTiming);
        cudaEventCreateWithFlags(&evB, cudaEventDisableTiming);
        cudaEventCreateWithFlags(&evP, cudaEventDisableTiming);
        cudaEventCreateWithFlags(&evC, cudaEventDisableTiming);
        cudaEventCreateWithFlags(&evD, cudaEventDisableTiming);
    }

    // fork side stream: prep + zero-seed xt + xl2/xr2 GEMM
    cudaEventRecord(evA, 0);
    cudaStreamWaitEvent(s1, evA, 0);
    prep_kernel<<<(NN_ * DIN / 4 + 255) / 256, 256, 0, s1>>>();
    cudaEventRecord(evP, s1);
    seed_xt_kernel<<<(E1_ * 32) / 256, 256, 0, s1>>>(out_xt);
    {
        dim3 gdim(DED / TBN, E1_ / TBM, 2);
        gemm_pipe<<<gdim, 256, SMEM_PIPE, s1>>>(x_trace, nullptr, e2n_Wl, e2n_Wr, e2n_bl, e2n_br,
                                                p_xl2, p_xr2, E1_, DED, DED);
    }
    cudaEventRecord(evB, s1);

    // main stream: xl/xr (dual-A, no concat) -> (wait prep) -> fused alpha1+agg1
    {
        dim3 gdim(DIN / TBN, NN_ / TBM, 2);
        gemm_pipe<<<gdim, 256, SMEM_PIPE>>>(x_node, x_log, n2n_Wl, n2n_Wr, n2n_bl, n2n_br,
                                            p_xl, p_xr, NN_, DIN, DIN);
    }
    cudaStreamWaitEvent(0, evP, 0);
    {
        dim3 gdim(DIN / TBN, E1_ / TBM);
        gemm_alpha1_agg1_fused<<<gdim, 256, SMEM_PIPE>>>(x_trace, n2n_We, node_adj, n2n_att);
    }
    cudaEventRecord(evC, 0);   // numerator + den1 final

    // side stream: write xn/xlg outputs while main does gfeat + alpha2_agg2
    cudaStreamWaitEvent(s1, evC, 0);
    write_node_out_kernel<<<(NN_ * 64) / 256, 256, 0, s1>>>(out, n2n_bias);
    cudaEventRecord(evD, s1);

    // main: gfeat = normalize(num) @ We2
    {
        dim3 gdim(1, NN_ / TBM);
        gemm_gfeat<<<gdim, 256, SMEM_PIPE>>>(p_num, p_den1, n2n_bias, e2n_We, p_g);
    }

    // join: merged layer-2 needs xl2/xr2 + seeded xt from side stream
    cudaStreamWaitEvent(0, evB, 0);

    alpha2_agg2_kernel<<<E2_ / 32, 256>>>(edge_adj, edge_efea, e2n_att, out_xt);
    normalize_xt_kernel<<<(E1_ * 32) / 256, 256>>>(out_xt, e2n_bias);

    // final join: node-out writes ordered into stream 0
    cudaStreamWaitEvent(0, evD, 0);
}